// round 6
// baseline (speedup 1.0000x reference)
#include <cuda_runtime.h>
#include <cstddef>

#define BB 64
#define TT 512
#define DD 1024
#define NN 64
#define SCORES_ELEMS (BB*TT*NN)
#define TAGS_OFF SCORES_ELEMS
#define LOSS_OFF (SCORES_ELEMS + BB*TT)

#define L2E 1.4426950408889634f
#define LN2 0.6931471805599453f

__device__ float g_logz[BB];
__device__ float g_gold[BB];

__device__ __forceinline__ float fast_ex2(float x){ float r; asm("ex2.approx.ftz.f32 %0, %1;" : "=f"(r) : "f"(x)); return r; }
__device__ __forceinline__ float fast_lg2(float x){ float r; asm("lg2.approx.ftz.f32 %0, %1;" : "=f"(r) : "f"(x)); return r; }

typedef unsigned long long ull;
__device__ __forceinline__ ull pk2(float x, float y){ ull r; asm("mov.b64 %0, {%1,%2};" : "=l"(r) : "f"(x), "f"(y)); return r; }
__device__ __forceinline__ void upk2(ull v, float& x, float& y){ asm("mov.b64 {%0,%1}, %2;" : "=f"(x), "=f"(y) : "l"(v)); }
__device__ __forceinline__ ull ffma2(ull a, ull b, ull c){ ull d; asm("fma.rn.f32x2 %0, %1, %2, %3;" : "=l"(d) : "l"(a), "l"(b), "l"(c)); return d; }

__device__ __forceinline__ void bar1_64(){ asm volatile("bar.sync 1, 64;" ::: "memory"); }
__device__ __forceinline__ void bar2_64(){ asm volatile("bar.sync 2, 64;" ::: "memory"); }

// ---------------------------------------------------------------------------
// GEMM, row-pair f32x2: grid 512 x 128 thr, tile 64 rows x 64 cols.
// Thread (tid&31 -> row-pair r2, tid>>5 -> 16-col group). Accumulators are
// (row r2, row r2+1) f32x2 pairs: A operand = direct LDS.64 from k-major As
// (no pk2), W operand = pre-duplicated (w,w) pairs in Ws2 (LDS.128 = 2 cols).
// Per thread per k: 16 FFMA2 + 1 LDS.64 + 8 LDS.128. Single buffer, KC=32.
// ---------------------------------------------------------------------------
#define KC 32
#define NCHUNK (DD/KC)
#define W2PITCH 132

__global__ __launch_bounds__(128, 4) void gemm_f32x2_kernel(
    const float* __restrict__ X, const float* __restrict__ W,
    const float* __restrict__ bias, const int* __restrict__ mask,
    float* __restrict__ out, float* __restrict__ out_loss)
{
    __shared__ __align__(16) float As[KC][64];         // 8192 B, k-major
    __shared__ __align__(16) float Ws2[KC][W2PITCH];   // 16896 B, duplicated cols

    const int tid = threadIdx.x;
    const int rowbase = blockIdx.x * 64;

    if (blockIdx.x == 0 && tid == 0) *out_loss = 0.f;

    // compute mapping
    const int r2  = (tid & 31) * 2;      // row pair
    const int c16 = (tid >> 5) * 16;     // col group (per warp)
    // A gmem load mapping: 2 lanes per row
    const int arow = tid >> 1;
    const int ah = tid & 1;
    const float* Xp = X + (size_t)(rowbase + arow) * DD + ah * 16;
    // W gmem load mapping
    const int kr = tid >> 2;             // 0..31
    const int wsoff = (tid & 3) * 16;    // 0,16,32,48
    const float* Wp = W + (size_t)kr * NN + wsoff;

    float4 xa[4], wb[4];
    ull acc[16];
    #pragma unroll
    for (int c = 0; c < 16; c++) acc[c] = 0ULL;

    // prologue: load + store chunk 0
    #pragma unroll
    for (int q = 0; q < 4; q++) xa[q] = *(const float4*)&Xp[q * 4];
    #pragma unroll
    for (int e = 0; e < 4; e++) wb[e] = *(const float4*)&Wp[e * 4];
    #pragma unroll
    for (int q = 0; q < 4; q++) {
        const int kq = ah * 16 + q * 4;
        As[kq + 0][arow] = xa[q].x; As[kq + 1][arow] = xa[q].y;
        As[kq + 2][arow] = xa[q].z; As[kq + 3][arow] = xa[q].w;
    }
    #pragma unroll
    for (int e = 0; e < 4; e++) {
        const int cb = wsoff + e * 4;
        *(ull*)&Ws2[kr][2*(cb+0)] = pk2(wb[e].x, wb[e].x);
        *(ull*)&Ws2[kr][2*(cb+1)] = pk2(wb[e].y, wb[e].y);
        *(ull*)&Ws2[kr][2*(cb+2)] = pk2(wb[e].z, wb[e].z);
        *(ull*)&Ws2[kr][2*(cb+3)] = pk2(wb[e].w, wb[e].w);
    }
    __syncthreads();

    for (int c = 0; c < NCHUNK; c++) {
        if (c + 1 < NCHUNK) {
            const int kk = (c + 1) * KC;
            #pragma unroll
            for (int q = 0; q < 4; q++) xa[q] = *(const float4*)&Xp[kk + q * 4];
            #pragma unroll
            for (int e = 0; e < 4; e++) wb[e] = *(const float4*)&Wp[(size_t)kk * NN + e * 4];
        }
        #pragma unroll 8
        for (int k = 0; k < KC; k++) {
            const ull apair = *(const ull*)&As[k][r2];
            #pragma unroll
            for (int p = 0; p < 8; p++) {
                ulonglong2 wd = *(const ulonglong2*)&Ws2[k][2*c16 + p*4];
                acc[2*p + 0] = ffma2(apair, wd.x, acc[2*p + 0]);
                acc[2*p + 1] = ffma2(apair, wd.y, acc[2*p + 1]);
            }
        }
        __syncthreads();
        if (c + 1 < NCHUNK) {
            #pragma unroll
            for (int q = 0; q < 4; q++) {
                const int kq = ah * 16 + q * 4;
                As[kq + 0][arow] = xa[q].x; As[kq + 1][arow] = xa[q].y;
                As[kq + 2][arow] = xa[q].z; As[kq + 3][arow] = xa[q].w;
            }
            #pragma unroll
            for (int e = 0; e < 4; e++) {
                const int cb = wsoff + e * 4;
                *(ull*)&Ws2[kr][2*(cb+0)] = pk2(wb[e].x, wb[e].x);
                *(ull*)&Ws2[kr][2*(cb+1)] = pk2(wb[e].y, wb[e].y);
                *(ull*)&Ws2[kr][2*(cb+2)] = pk2(wb[e].z, wb[e].z);
                *(ull*)&Ws2[kr][2*(cb+3)] = pk2(wb[e].w, wb[e].w);
            }
            __syncthreads();
        }
    }

    // epilogue: rows r2, r2+1, cols c16..c16+15
    const int row0 = rowbase + r2;
    const float mf0 = (float)mask[row0];
    const float mf1 = (float)mask[row0 + 1];
    float vlo[16], vhi[16];
    #pragma unroll
    for (int c = 0; c < 16; c++) upk2(acc[c], vlo[c], vhi[c]);
    #pragma unroll
    for (int e = 0; e < 4; e++) {
        float4 bv = *(const float4*)&bias[c16 + e * 4];
        float4 o0, o1;
        o0.x = (vlo[e*4+0] + bv.x) * mf0; o0.y = (vlo[e*4+1] + bv.y) * mf0;
        o0.z = (vlo[e*4+2] + bv.z) * mf0; o0.w = (vlo[e*4+3] + bv.w) * mf0;
        o1.x = (vhi[e*4+0] + bv.x) * mf1; o1.y = (vhi[e*4+1] + bv.y) * mf1;
        o1.z = (vhi[e*4+2] + bv.z) * mf1; o1.w = (vhi[e*4+3] + bv.w) * mf1;
        *(float4*)&out[(size_t)row0 * NN + c16 + e * 4]       = o0;
        *(float4*)&out[(size_t)(row0 + 1) * NN + c16 + e * 4] = o1;
    }
}

// ---------------------------------------------------------------------------
// CRF kernel: blocks 0..63 = log-partition (threads 0-63) + gold (64-127);
// blocks 64..127 = Viterbi with FMNMX-tree argmax.
// ---------------------------------------------------------------------------
struct VitSm {
    unsigned char bp[(TT - 1) * NN];
    float alphaS[2][NN];
    int   tag[TT];
};
struct LseSm {
    float pS[2][NN];
    float redf[2];
    int   redi[2];
    float logz_s, gold_s;
};
union CrfSm { VitSm v; LseSm l; };

__global__ __launch_bounds__(128) void crf_kernel(
    const float* __restrict__ scores, const int* __restrict__ mask,
    const int* __restrict__ labels, const float* __restrict__ trans,
    const float* __restrict__ startv, const float* __restrict__ endv,
    float* __restrict__ out_tags, float* __restrict__ out_loss)
{
    __shared__ __align__(16) CrfSm sm;
    const int tid = threadIdx.x;

    if (blockIdx.x < BB) {
        const int b = blockIdx.x;
        if (tid < 64) {
            // ============ LOG PARTITION =============
            const int j = tid;
            unsigned mkb[TT/32];
            #pragma unroll
            for (int w = 0; w < TT/32; w++)
                mkb[w] = __ballot_sync(0xffffffffu, mask[b * TT + w * 32 + (tid & 31)] != 0);

            ull E2[NN/2];
            #pragma unroll
            for (int i2 = 0; i2 < NN/2; i2++) {
                float e0 = fast_ex2(trans[(2*i2)     * NN + j] * L2E);
                float e1 = fast_ex2(trans[(2*i2 + 1) * NN + j] * L2E);
                E2[i2] = pk2(e0, e1);
            }

            const float* srow = scores + (size_t)b * TT * NN + j;
            float alpha = startv[j] + srow[0];
            const float m0 = startv[0] + scores[(size_t)b * TT * NN];
            float Mref = m0;
            sm.l.pS[0][j] = fast_ex2((alpha - m0) * L2E);

            float ecur = srow[NN];
            float enext = srow[2 * NN];
            bar1_64();

            for (int t = 1; t < TT; t++) {
                const int pb = (t - 1) & 1, cb = t & 1;
                float p0 = sm.l.pS[pb][0];
                const float mNew = fmaf(fast_lg2(p0), LN2, Mref);
                ull a0 = 0ULL, a1 = 0ULL, a2 = 0ULL, a3 = 0ULL;
                #pragma unroll
                for (int i = 0; i < NN; i += 8) {
                    ulonglong2 q0 = *(const ulonglong2*)&sm.l.pS[pb][i];
                    ulonglong2 q1 = *(const ulonglong2*)&sm.l.pS[pb][i + 4];
                    a0 = ffma2(q0.x, E2[i/2],     a0);
                    a1 = ffma2(q0.y, E2[i/2 + 1], a1);
                    a2 = ffma2(q1.x, E2[i/2 + 2], a2);
                    a3 = ffma2(q1.y, E2[i/2 + 3], a3);
                }
                float f0,f1,f2,f3,f4,f5,f6,f7;
                upk2(a0,f0,f1); upk2(a1,f2,f3); upk2(a2,f4,f5); upk2(a3,f6,f7);
                float s = ((f0+f1)+(f2+f3)) + ((f4+f5)+(f6+f7));
                float cand = fmaf(fast_lg2(s), LN2, Mref) + ecur;
                const int bit = (mkb[t >> 5] >> (t & 31)) & 1;
                if (bit) alpha = cand;
                sm.l.pS[cb][j] = fast_ex2((alpha - mNew) * L2E);
                Mref = mNew;
                ecur = enext;
                if (t + 2 < TT) enext = srow[(size_t)(t + 2) * NN];
                bar1_64();
            }
            sm.l.pS[0][j] = alpha + endv[j];
            bar1_64();
            if (tid < 32) {
                float v0 = sm.l.pS[0][tid], v1 = sm.l.pS[0][tid + 32];
                float m2 = sm.l.pS[0][0];
                float ss = fast_ex2((v0 - m2) * L2E) + fast_ex2((v1 - m2) * L2E);
                #pragma unroll
                for (int off = 16; off; off >>= 1) ss += __shfl_xor_sync(0xffffffffu, ss, off);
                if (tid == 0) {
                    float lz = fmaf(fast_lg2(ss), LN2, m2);
                    g_logz[b] = lz;
                    sm.l.logz_s = lz;
                }
            }
        } else {
            // ============ GOLD SCORE (concurrent) ==========
            const int gt = tid - 64;
            float acc = 0.f; int cnt = 0;
            for (int t = gt; t < TT; t += 64) {
                const int mkv = mask[b * TT + t];
                const int lt = labels[b * TT + t];
                const float mf = (float)mkv;
                acc += scores[((size_t)(b * TT + t)) * NN + lt] * mf;
                if (t > 0) {
                    const int lp = labels[b * TT + t - 1];
                    acc += trans[lp * NN + lt] * mf;
                }
                cnt += mkv;
            }
            #pragma unroll
            for (int off = 16; off; off >>= 1) {
                acc += __shfl_xor_sync(0xffffffffu, acc, off);
                cnt += __shfl_xor_sync(0xffffffffu, cnt, off);
            }
            if ((gt & 31) == 0) { sm.l.redf[gt >> 5] = acc; sm.l.redi[gt >> 5] = cnt; }
            bar2_64();
            if (gt == 0) {
                float a = sm.l.redf[0] + sm.l.redf[1];
                int c = sm.l.redi[0] + sm.l.redi[1];
                float gd = a + startv[labels[b * TT]] + endv[labels[b * TT + c - 1]];
                g_gold[b] = gd;
                sm.l.gold_s = gd;
            }
        }
        __syncthreads();
        if (tid == 0)
            atomicAdd(out_loss, (sm.l.logz_s - sm.l.gold_s) * (1.0f / 64.0f));
    } else {
        // ================= VITERBI (128 threads, 2/tag) =====================
        const int b = blockIdx.x - BB;
        const int j = tid >> 1;
        const int h = tid & 1;
        const int i0 = h * 32;

        unsigned mkb[TT/32];
        #pragma unroll
        for (int w = 0; w < TT/32; w++)
            mkb[w] = __ballot_sync(0xffffffffu, mask[b * TT + w * 32 + (tid & 31)] != 0);

        float Tr[32];
        #pragma unroll
        for (int i = 0; i < 32; i++) Tr[i] = trans[(i0 + i) * NN + j];

        const float* srow = scores + (size_t)b * TT * NN + j;
        float alpha = 0.f;
        if (h == 0) { alpha = startv[j] + srow[0]; sm.v.alphaS[0][j] = alpha; }
        float ecur = srow[NN];
        float enext = srow[2 * NN];
        __syncthreads();

        for (int t = 1; t < TT; t++) {
            const int pb = (t - 1) & 1, cb = t & 1;
            float v[32];
            #pragma unroll
            for (int c = 0; c < 8; c++) {
                float4 av = *(const float4*)&sm.v.alphaS[pb][i0 + c * 4];
                v[c*4+0] = av.x + Tr[c*4+0];
                v[c*4+1] = av.y + Tr[c*4+1];
                v[c*4+2] = av.z + Tr[c*4+2];
                v[c*4+3] = av.w + Tr[c*4+3];
            }
            // max via FMNMX tree (all 4-cyc pipelined ops)
            float w16[16];
            #pragma unroll
            for (int i = 0; i < 16; i++) w16[i] = fmaxf(v[i], v[i + 16]);
            #pragma unroll
            for (int i = 0; i < 8; i++)  w16[i] = fmaxf(w16[i], w16[i + 8]);
            #pragma unroll
            for (int i = 0; i < 4; i++)  w16[i] = fmaxf(w16[i], w16[i + 4]);
            float bm = fmaxf(fmaxf(w16[0], w16[2]), fmaxf(w16[1], w16[3]));
            // first index achieving the max (pipelined equality scan)
            int idx = 999;
            #pragma unroll
            for (int i = 0; i < 32; i++) idx = min(idx, (v[i] == bm) ? i : 999);
            idx += i0;
            // combine halves (h=0 holds smaller indices)
            const float vo = __shfl_xor_sync(0xffffffffu, bm, 1);
            const int   io = __shfl_xor_sync(0xffffffffu, idx, 1);
            const float bAll = fmaxf(bm, vo);
            const int c1 = (bm == bAll) ? idx : 1999;
            const int c2 = (vo == bAll) ? io  : 1999;
            const int bi = min(c1, c2);
            if (h == 0) {
                const int bit = (mkb[t >> 5] >> (t & 31)) & 1;
                sm.v.bp[(t - 1) * NN + j] = (unsigned char)(bit ? bi : j);
                if (bit) alpha = bAll + ecur;
                sm.v.alphaS[cb][j] = alpha;
            }
            ecur = enext;
            if (t + 2 < TT) enext = srow[(size_t)(t + 2) * NN];
            __syncthreads();
        }
        if (tid == 0) {
            const int fb = (TT - 1) & 1;
            float bestf = -1e30f; int cur = 0;
            for (int jj = 0; jj < NN; jj++) {
                float vv = sm.v.alphaS[fb][jj] + endv[jj];
                if (vv > bestf) { bestf = vv; cur = jj; }
            }
            sm.v.tag[TT - 1] = cur;
            for (int t = TT - 1; t >= 1; t--) {
                cur = sm.v.bp[(t - 1) * NN + cur];
                sm.v.tag[t - 1] = cur;
            }
        }
        __syncthreads();
        for (int t = tid; t < TT; t += 128) {
            const int bit = (mkb[t >> 5] >> (t & 31)) & 1;
            out_tags[b * TT + t] = (float)(sm.v.tag[t] * bit);
        }
    }
}

extern "C" void kernel_launch(void* const* d_in, const int* in_sizes, int n_in,
                              void* d_out, int out_size) {
    const float* X      = (const float*)d_in[0];
    const int*   mask   = (const int*)d_in[1];
    const int*   labels = (const int*)d_in[2];
    const float* W      = (const float*)d_in[3];
    const float* bias   = (const float*)d_in[4];
    const float* trans  = (const float*)d_in[5];
    const float* startv = (const float*)d_in[6];
    const float* endv   = (const float*)d_in[7];
    float* out = (float*)d_out;

    gemm_f32x2_kernel<<<512, 128>>>(X, W, bias, mask, out, out + LOSS_OFF);
    crf_kernel<<<128, 128>>>(out, mask, labels, trans, startv, endv,
                             out + TAGS_OFF, out + LOSS_OFF);
}

// round 7
// speedup vs baseline: 1.7944x; 1.7944x over previous
#include <cuda_runtime.h>
#include <cstddef>

#define BB 64
#define TT 512
#define DD 1024
#define NN 64
#define SCORES_ELEMS (BB*TT*NN)
#define TAGS_OFF SCORES_ELEMS
#define LOSS_OFF (SCORES_ELEMS + BB*TT)

#define L2E 1.4426950408889634f
#define LN2 0.6931471805599453f

__device__ float g_logz[BB];
__device__ float g_gold[BB];

__device__ __forceinline__ float fast_ex2(float x){ float r; asm("ex2.approx.ftz.f32 %0, %1;" : "=f"(r) : "f"(x)); return r; }
__device__ __forceinline__ float fast_lg2(float x){ float r; asm("lg2.approx.ftz.f32 %0, %1;" : "=f"(r) : "f"(x)); return r; }

typedef unsigned long long ull;
__device__ __forceinline__ ull pk2(float x, float y){ ull r; asm("mov.b64 %0, {%1,%2};" : "=l"(r) : "f"(x), "f"(y)); return r; }
__device__ __forceinline__ void upk2(ull v, float& x, float& y){ asm("mov.b64 {%0,%1}, %2;" : "=f"(x), "=f"(y) : "l"(v)); }
__device__ __forceinline__ ull ffma2(ull a, ull b, ull c){ ull d; asm("fma.rn.f32x2 %0, %1, %2, %3;" : "=l"(d) : "l"(a), "l"(b), "l"(c)); return d; }

__device__ __forceinline__ void barA(){ asm volatile("bar.sync 1, 128;" ::: "memory"); }
__device__ __forceinline__ void barB(){ asm volatile("bar.sync 2, 128;" ::: "memory"); }

// ---------------------------------------------------------------------------
// GEMM (R3 config, measured 152.8us): 256 CTAs x 128 threads, tile 128x64,
// 8x8/thread, f32x2 on column pairs, KC=32 double-buffered, 1B-smem/FMA.
// ---------------------------------------------------------------------------
#define KC 32
#define NCHUNK (DD/KC)

__global__ __launch_bounds__(128, 3) void gemm_f32x2_kernel(
    const float* __restrict__ X, const float* __restrict__ W,
    const float* __restrict__ bias, const int* __restrict__ mask,
    float* __restrict__ out, float* __restrict__ out_loss)
{
    __shared__ __align__(16) float As[2][KC][128];   // 32768 B
    __shared__ __align__(16) float Ws[2][KC][64];    // 16384 B

    const int tid = threadIdx.x;
    const int rg = tid >> 3;        // 0..15
    const int cg = tid & 7;         // 0..7
    const int r8 = rg * 8, c8 = cg * 8;
    const int rowbase = blockIdx.x * 128;

    if (blockIdx.x == 0 && tid == 0) *out_loss = 0.f;

    const float* Xrow = X + (size_t)(rowbase + tid) * DD;
    const int kr = tid >> 2;            // 0..31
    const int wsoff = (tid & 3) * 16;   // 0,16,32,48

    float4 xa[8], wb[4];

    ull acc[8][4];
    #pragma unroll
    for (int r = 0; r < 8; r++)
        #pragma unroll
        for (int p = 0; p < 4; p++) acc[r][p] = 0ULL;

    // prologue: chunk 0
    #pragma unroll
    for (int q = 0; q < 8; q++) xa[q] = *(const float4*)&Xrow[q * 4];
    #pragma unroll
    for (int e = 0; e < 4; e++) wb[e] = *(const float4*)&W[(size_t)kr * NN + wsoff + e * 4];
    #pragma unroll
    for (int q = 0; q < 8; q++) {
        As[0][q*4+0][tid] = xa[q].x; As[0][q*4+1][tid] = xa[q].y;
        As[0][q*4+2][tid] = xa[q].z; As[0][q*4+3][tid] = xa[q].w;
    }
    #pragma unroll
    for (int e = 0; e < 4; e++) *(float4*)&Ws[0][kr][wsoff + e * 4] = wb[e];
    __syncthreads();

    for (int c = 0; c < NCHUNK; c++) {
        if (c + 1 < NCHUNK) {
            const int kk = (c + 1) * KC;
            #pragma unroll
            for (int q = 0; q < 8; q++) xa[q] = *(const float4*)&Xrow[kk + q * 4];
            #pragma unroll
            for (int e = 0; e < 4; e++) wb[e] = *(const float4*)&W[(size_t)(kk + kr) * NN + wsoff + e * 4];
        }
        const int buf = c & 1;
        #pragma unroll 8
        for (int k = 0; k < KC; k++) {
            float4 a0 = *(const float4*)&As[buf][k][r8];
            float4 a1 = *(const float4*)&As[buf][k][r8 + 4];
            ulonglong2 w0 = *(const ulonglong2*)&Ws[buf][k][c8];
            ulonglong2 w1 = *(const ulonglong2*)&Ws[buf][k][c8 + 4];
            ull A[8];
            A[0] = pk2(a0.x, a0.x); A[1] = pk2(a0.y, a0.y);
            A[2] = pk2(a0.z, a0.z); A[3] = pk2(a0.w, a0.w);
            A[4] = pk2(a1.x, a1.x); A[5] = pk2(a1.y, a1.y);
            A[6] = pk2(a1.z, a1.z); A[7] = pk2(a1.w, a1.w);
            #pragma unroll
            for (int r = 0; r < 8; r++) {
                acc[r][0] = ffma2(A[r], w0.x, acc[r][0]);
                acc[r][1] = ffma2(A[r], w0.y, acc[r][1]);
                acc[r][2] = ffma2(A[r], w1.x, acc[r][2]);
                acc[r][3] = ffma2(A[r], w1.y, acc[r][3]);
            }
        }
        __syncthreads();
        if (c + 1 < NCHUNK) {
            const int nb = (c + 1) & 1;
            #pragma unroll
            for (int q = 0; q < 8; q++) {
                As[nb][q*4+0][tid] = xa[q].x; As[nb][q*4+1][tid] = xa[q].y;
                As[nb][q*4+2][tid] = xa[q].z; As[nb][q*4+3][tid] = xa[q].w;
            }
            #pragma unroll
            for (int e = 0; e < 4; e++) *(float4*)&Ws[nb][kr][wsoff + e * 4] = wb[e];
            __syncthreads();
        }
    }

    float bs[8];
    #pragma unroll
    for (int e = 0; e < 8; e++) bs[e] = bias[c8 + e];
    #pragma unroll
    for (int r = 0; r < 8; r++) {
        const int row = rowbase + r8 + r;
        const float mf = (float)mask[row];
        float v[8];
        upk2(acc[r][0], v[0], v[1]); upk2(acc[r][1], v[2], v[3]);
        upk2(acc[r][2], v[4], v[5]); upk2(acc[r][3], v[6], v[7]);
        float4 o0, o1;
        o0.x = (v[0]+bs[0])*mf; o0.y = (v[1]+bs[1])*mf; o0.z = (v[2]+bs[2])*mf; o0.w = (v[3]+bs[3])*mf;
        o1.x = (v[4]+bs[4])*mf; o1.y = (v[5]+bs[5])*mf; o1.z = (v[6]+bs[6])*mf; o1.w = (v[7]+bs[7])*mf;
        *(float4*)&out[(size_t)row * NN + c8]     = o0;
        *(float4*)&out[(size_t)row * NN + c8 + 4] = o1;
    }
}

// ---------------------------------------------------------------------------
// CRF kernel, 256 threads/CTA.
// Blocks 0..63: LSE on threads 0-127 (2 threads/tag) + gold on 128-255.
// Blocks 64..127: Viterbi, 4 threads/tag (16 sources each).
// ---------------------------------------------------------------------------
struct VitSm {
    unsigned char bp[(TT - 1) * NN];
    float alphaS[2][NN];
    int   tag[TT];
};
struct LseSm {
    float pS[2][NN];
    float redf[4];
    int   redi[4];
    float logz_s, gold_s;
};
union CrfSm { VitSm v; LseSm l; };

__global__ __launch_bounds__(256) void crf_kernel(
    const float* __restrict__ scores, const int* __restrict__ mask,
    const int* __restrict__ labels, const float* __restrict__ trans,
    const float* __restrict__ startv, const float* __restrict__ endv,
    float* __restrict__ out_tags, float* __restrict__ out_loss)
{
    __shared__ __align__(16) CrfSm sm;
    const int tid = threadIdx.x;

    if (blockIdx.x < BB) {
        const int b = blockIdx.x;
        if (tid < 128) {
            // ===== LOG PARTITION: 2 threads per tag, j=tid>>1, h=tid&1 ======
            const int j = tid >> 1;
            const int h = tid & 1;
            const int i0 = h * 32;

            unsigned mkb[TT/32];
            #pragma unroll
            for (int w = 0; w < TT/32; w++)
                mkb[w] = __ballot_sync(0xffffffffu, mask[b * TT + w * 32 + (tid & 31)] != 0);

            // E over this thread's 32 sources, packed in pairs
            ull E2[16];
            #pragma unroll
            for (int i2 = 0; i2 < 16; i2++) {
                float e0 = fast_ex2(trans[(i0 + 2*i2)     * NN + j] * L2E);
                float e1 = fast_ex2(trans[(i0 + 2*i2 + 1) * NN + j] * L2E);
                E2[i2] = pk2(e0, e1);
            }

            const float* srow = scores + (size_t)b * TT * NN + j;
            float alpha = startv[j] + srow[0];
            const float m0 = startv[0] + scores[(size_t)b * TT * NN];
            float Mref = m0;
            if (h == 0) sm.l.pS[0][j] = fast_ex2((alpha - m0) * L2E);

            float ecur = srow[NN];
            float enext = srow[2 * NN];
            barA();

            for (int t = 1; t < TT; t++) {
                const int pb = (t - 1) & 1, cb = t & 1;
                float p0 = sm.l.pS[pb][0];
                const float mNew = fmaf(fast_lg2(p0), LN2, Mref);   // alpha0^(t-1)
                ulonglong2 q0 = *(const ulonglong2*)&sm.l.pS[pb][i0];
                ulonglong2 q1 = *(const ulonglong2*)&sm.l.pS[pb][i0 + 4];
                ulonglong2 q2 = *(const ulonglong2*)&sm.l.pS[pb][i0 + 8];
                ulonglong2 q3 = *(const ulonglong2*)&sm.l.pS[pb][i0 + 12];
                ulonglong2 q4 = *(const ulonglong2*)&sm.l.pS[pb][i0 + 16];
                ulonglong2 q5 = *(const ulonglong2*)&sm.l.pS[pb][i0 + 20];
                ulonglong2 q6 = *(const ulonglong2*)&sm.l.pS[pb][i0 + 24];
                ulonglong2 q7 = *(const ulonglong2*)&sm.l.pS[pb][i0 + 28];
                ull a0 = 0ULL, a1 = 0ULL, a2 = 0ULL, a3 = 0ULL;
                a0 = ffma2(q0.x, E2[0],  a0); a1 = ffma2(q0.y, E2[1],  a1);
                a2 = ffma2(q1.x, E2[2],  a2); a3 = ffma2(q1.y, E2[3],  a3);
                a0 = ffma2(q2.x, E2[4],  a0); a1 = ffma2(q2.y, E2[5],  a1);
                a2 = ffma2(q3.x, E2[6],  a2); a3 = ffma2(q3.y, E2[7],  a3);
                a0 = ffma2(q4.x, E2[8],  a0); a1 = ffma2(q4.y, E2[9],  a1);
                a2 = ffma2(q5.x, E2[10], a2); a3 = ffma2(q5.y, E2[11], a3);
                a0 = ffma2(q6.x, E2[12], a0); a1 = ffma2(q6.y, E2[13], a1);
                a2 = ffma2(q7.x, E2[14], a2); a3 = ffma2(q7.y, E2[15], a3);
                float f0,f1,f2,f3,f4,f5,f6,f7;
                upk2(a0,f0,f1); upk2(a1,f2,f3); upk2(a2,f4,f5); upk2(a3,f6,f7);
                float sh = ((f0+f1)+(f2+f3)) + ((f4+f5)+(f6+f7));
                float s = sh + __shfl_xor_sync(0xffffffffu, sh, 1);
                float cand = fmaf(fast_lg2(s), LN2, Mref) + ecur;
                const int bit = (mkb[t >> 5] >> (t & 31)) & 1;
                if (bit) alpha = cand;
                if (h == 0) sm.l.pS[cb][j] = fast_ex2((alpha - mNew) * L2E);
                Mref = mNew;
                ecur = enext;
                if (t + 2 < TT) enext = srow[(size_t)(t + 2) * NN];
                barA();
            }
            if (h == 0) sm.l.pS[0][j] = alpha + endv[j];
            barA();
            if (tid < 32) {
                float v0 = sm.l.pS[0][tid], v1 = sm.l.pS[0][tid + 32];
                float m2 = sm.l.pS[0][0];
                float ss = fast_ex2((v0 - m2) * L2E) + fast_ex2((v1 - m2) * L2E);
                #pragma unroll
                for (int off = 16; off; off >>= 1) ss += __shfl_xor_sync(0xffffffffu, ss, off);
                if (tid == 0) {
                    float lz = fmaf(fast_lg2(ss), LN2, m2);
                    g_logz[b] = lz;
                    sm.l.logz_s = lz;
                }
            }
        } else {
            // ============ GOLD SCORE (threads 128..255, concurrent) =========
            const int gt = tid - 128;
            float acc = 0.f; int cnt = 0;
            for (int t = gt; t < TT; t += 128) {
                const int mkv = mask[b * TT + t];
                const int lt = labels[b * TT + t];
                const float mf = (float)mkv;
                acc += scores[((size_t)(b * TT + t)) * NN + lt] * mf;
                if (t > 0) {
                    const int lp = labels[b * TT + t - 1];
                    acc += trans[lp * NN + lt] * mf;
                }
                cnt += mkv;
            }
            #pragma unroll
            for (int off = 16; off; off >>= 1) {
                acc += __shfl_xor_sync(0xffffffffu, acc, off);
                cnt += __shfl_xor_sync(0xffffffffu, cnt, off);
            }
            if ((gt & 31) == 0) { sm.l.redf[gt >> 5] = acc; sm.l.redi[gt >> 5] = cnt; }
            barB();
            if (gt == 0) {
                float a = sm.l.redf[0] + sm.l.redf[1] + sm.l.redf[2] + sm.l.redf[3];
                int c = sm.l.redi[0] + sm.l.redi[1] + sm.l.redi[2] + sm.l.redi[3];
                float gd = a + startv[labels[b * TT]] + endv[labels[b * TT + c - 1]];
                g_gold[b] = gd;
                sm.l.gold_s = gd;
            }
        }
        __syncthreads();
        if (tid == 0)
            atomicAdd(out_loss, (sm.l.logz_s - sm.l.gold_s) * (1.0f / 64.0f));
    } else {
        // ============ VITERBI: 4 threads/tag, j=tid>>2, h=tid&3 =============
        const int b = blockIdx.x - BB;
        const int j = tid >> 2;
        const int h = tid & 3;
        const int i0 = h * 16;

        unsigned mkb[TT/32];
        #pragma unroll
        for (int w = 0; w < TT/32; w++)
            mkb[w] = __ballot_sync(0xffffffffu, mask[b * TT + w * 32 + (tid & 31)] != 0);

        float Tr[16];
        #pragma unroll
        for (int i = 0; i < 16; i++) Tr[i] = trans[(i0 + i) * NN + j];

        const float* srow = scores + (size_t)b * TT * NN + j;
        float alpha = 0.f;
        if (h == 0) { alpha = startv[j] + srow[0]; sm.v.alphaS[0][j] = alpha; }
        float ecur = srow[NN];
        float enext = srow[2 * NN];
        __syncthreads();

        for (int t = 1; t < TT; t++) {
            const int pb = (t - 1) & 1, cb = t & 1;
            // 4 ascending chains of 4
            float bv[4]; int bx[4];
            #pragma unroll
            for (int c = 0; c < 4; c++) {
                float4 av = *(const float4*)&sm.v.alphaS[pb][i0 + c * 4];
                float v0 = av.x + Tr[c*4+0];
                float v1 = av.y + Tr[c*4+1];
                float v2 = av.z + Tr[c*4+2];
                float v3 = av.w + Tr[c*4+3];
                float cbv = v0; int ci = i0 + c*4;
                if (v1 > cbv) { cbv = v1; ci = i0 + c*4 + 1; }
                if (v2 > cbv) { cbv = v2; ci = i0 + c*4 + 2; }
                if (v3 > cbv) { cbv = v3; ci = i0 + c*4 + 3; }
                bv[c] = cbv; bx[c] = ci;
            }
            float best = bv[0]; int bi = bx[0];
            #pragma unroll
            for (int c = 1; c < 4; c++)
                if (bv[c] > best || (bv[c] == best && bx[c] < bi)) { best = bv[c]; bi = bx[c]; }
            // merge across the 4 h-threads (indices fully ordered by tie rule)
            {
                const float vo = __shfl_xor_sync(0xffffffffu, best, 1);
                const int   io = __shfl_xor_sync(0xffffffffu, bi, 1);
                if (vo > best || (vo == best && io < bi)) { best = vo; bi = io; }
            }
            {
                const float vo = __shfl_xor_sync(0xffffffffu, best, 2);
                const int   io = __shfl_xor_sync(0xffffffffu, bi, 2);
                if (vo > best || (vo == best && io < bi)) { best = vo; bi = io; }
            }
            if (h == 0) {
                const int bit = (mkb[t >> 5] >> (t & 31)) & 1;
                sm.v.bp[(t - 1) * NN + j] = (unsigned char)(bit ? bi : j);
                if (bit) alpha = best + ecur;
                sm.v.alphaS[cb][j] = alpha;
            }
            ecur = enext;
            if (t + 2 < TT) enext = srow[(size_t)(t + 2) * NN];
            __syncthreads();
        }
        if (tid == 0) {
            const int fb = (TT - 1) & 1;
            float bestf = -1e30f; int cur = 0;
            for (int jj = 0; jj < NN; jj++) {
                float vv = sm.v.alphaS[fb][jj] + endv[jj];
                if (vv > bestf) { bestf = vv; cur = jj; }
            }
            sm.v.tag[TT - 1] = cur;
            for (int t = TT - 1; t >= 1; t--) {
                cur = sm.v.bp[(t - 1) * NN + cur];
                sm.v.tag[t - 1] = cur;
            }
        }
        __syncthreads();
        for (int t = tid; t < TT; t += 256) {
            const int bit = (mkb[t >> 5] >> (t & 31)) & 1;
            out_tags[b * TT + t] = (float)(sm.v.tag[t] * bit);
        }
    }
}

extern "C" void kernel_launch(void* const* d_in, const int* in_sizes, int n_in,
                              void* d_out, int out_size) {
    const float* X      = (const float*)d_in[0];
    const int*   mask   = (const int*)d_in[1];
    const int*   labels = (const int*)d_in[2];
    const float* W      = (const float*)d_in[3];
    const float* bias   = (const float*)d_in[4];
    const float* trans  = (const float*)d_in[5];
    const float* startv = (const float*)d_in[6];
    const float* endv   = (const float*)d_in[7];
    float* out = (float*)d_out;

    gemm_f32x2_kernel<<<256, 128>>>(X, W, bias, mask, out, out + LOSS_OFF);
    crf_kernel<<<128, 256>>>(out, mask, labels, trans, startv, endv,
                             out + TAGS_OFF, out + LOSS_OFF);
}